// round 16
// baseline (speedup 1.0000x reference)
#include <cuda_runtime.h>
#include <cuda_fp16.h>
#include <cstdint>
#include <cstddef>

// ============================================================================
// SparseLinear: y[8192,4096] = x[8192,4096] @ W[4096,4096] + bias[4096]
// Dense fp16 mma.sync GEMM (tcgen05 blocked by compute_103 PTX target).
// R16: occupancy 2 CTAs/SM. BM=BN=128, BK=64, 3 stages (96KB/CTA), 256 thr,
//      warp tile 64x32, single-buffered fragments (regs ~115 < 128 cap) —
//      trades R4's ILP double-buffer for cross-warp/cross-CTA TLP: 4 warps
//      per SMSP hide ldsm RAW stalls and barrier waits.
// ============================================================================

#define D_DIM 4096
#define M_DIM 8192
#define BM 128
#define BN 128
#define BK 64
#define STAGES 3
#define KTILES (D_DIM / BK)            // 64
#define THREADS 256
#define A_TILE_BYTES (BM * BK * 2)     // 16384
#define B_TILE_BYTES (BN * BK * 2)     // 16384
#define STAGE_BYTES (A_TILE_BYTES + B_TILE_BYTES)   // 32768
#define SMEM_SIZE (STAGES * STAGE_BYTES)            // 98304

__device__ __align__(256) __half g_XH[(size_t)M_DIM * D_DIM];
__device__ __align__(256) __half g_WTH[(size_t)D_DIM * D_DIM];

// ---------------------------------------------------------------------------
// helpers
// ---------------------------------------------------------------------------
__device__ __forceinline__ uint32_t smem_u32(const void* p) {
    uint32_t a;
    asm("{ .reg .u64 t; cvta.to.shared.u64 t, %1; cvt.u32.u64 %0, t; }"
        : "=r"(a) : "l"(p));
    return a;
}

__device__ __forceinline__ void cp_async16(uint32_t dst, const void* src) {
    asm volatile("cp.async.cg.shared.global [%0], [%1], 16;"
                 :: "r"(dst), "l"(src));
}
__device__ __forceinline__ void cp_commit() {
    asm volatile("cp.async.commit_group;" ::: "memory");
}

__device__ __forceinline__ void ldsm_x4(uint32_t* r, uint32_t addr) {
    asm volatile("ldmatrix.sync.aligned.m8n8.x4.shared.b16 {%0,%1,%2,%3}, [%4];"
                 : "=r"(r[0]), "=r"(r[1]), "=r"(r[2]), "=r"(r[3])
                 : "r"(addr));
}

__device__ __forceinline__ void mma16816(float* c, const uint32_t* a,
                                         uint32_t b0, uint32_t b1) {
    asm volatile(
        "mma.sync.aligned.m16n8k16.row.col.f32.f16.f16.f32 "
        "{%0,%1,%2,%3}, {%4,%5,%6,%7}, {%8,%9}, {%0,%1,%2,%3};"
        : "+f"(c[0]), "+f"(c[1]), "+f"(c[2]), "+f"(c[3])
        : "r"(a[0]), "r"(a[1]), "r"(a[2]), "r"(a[3]), "r"(b0), "r"(b1));
}

// ---------------------------------------------------------------------------
// Merged prep (proven R15): x convert 32B/thread; 64x64 W-transpose tiles.
// ---------------------------------------------------------------------------
#define XBLK2 ((int)((size_t)M_DIM * D_DIM / 8 / 256))   // 16384

__global__ void prep_kernel(const float4* __restrict__ x,
                            const float* __restrict__ W) {
    if (blockIdx.x < XBLK2) {
        size_t i = (size_t)blockIdx.x * 256 + threadIdx.x;
        float4 v0 = x[2 * i];
        float4 v1 = x[2 * i + 1];
        __half2 h0 = __floats2half2_rn(v0.x, v0.y);
        __half2 h1 = __floats2half2_rn(v0.z, v0.w);
        __half2 h2 = __floats2half2_rn(v1.x, v1.y);
        __half2 h3 = __floats2half2_rn(v1.z, v1.w);
        uint4 o;
        o.x = *reinterpret_cast<uint32_t*>(&h0);
        o.y = *reinterpret_cast<uint32_t*>(&h1);
        o.z = *reinterpret_cast<uint32_t*>(&h2);
        o.w = *reinterpret_cast<uint32_t*>(&h3);
        reinterpret_cast<uint4*>(g_XH)[i] = o;
    } else {
        __shared__ float t[64][65];    // t[n_local][k_local]
        int b = blockIdx.x - XBLK2;                    // 64 x 64 tile grid
        int bx = (b & 63) * 64, by = (b >> 6) * 64;    // bx: n, by: k
        const int nx = threadIdx.x & 63, ky = threadIdx.x >> 6;
#pragma unroll
        for (int i = 0; i < 16; i++)
            t[nx][ky + i * 4] = W[(size_t)(by + ky + i * 4) * D_DIM + bx + nx];
        __syncthreads();
#pragma unroll
        for (int i = 0; i < 8; i++) {
            int idx = threadIdx.x + i * 256;
            int nl = idx >> 5, c = idx & 31;
            float va = t[nl][2 * c];
            float vb = t[nl][2 * c + 1];
            __half2 h = __floats2half2_rn(va, vb);
            *reinterpret_cast<uint32_t*>(
                g_WTH + (size_t)(bx + nl) * D_DIM + by + 2 * c) =
                *reinterpret_cast<uint32_t*>(&h);
        }
    }
}

// ---------------------------------------------------------------------------
// GEMM. grid (32, 64) = 2048 CTAs, 2 CTAs/SM. 8 warps (2m x 4n), warp 64x32.
// SMEM stage: [A 128x64 | B 128x64] halves, 128B rows, granule-XOR swizzle.
// ---------------------------------------------------------------------------
__global__ __launch_bounds__(THREADS, 2)
void gemm_f16_kernel(const float* __restrict__ bias, float* __restrict__ out) {
    extern __shared__ char smem[];
    const uint32_t sbase = smem_u32(smem);
    const int tid = threadIdx.x;
    const int wid = tid >> 5;
    const int l = tid & 31;
    const int bm = blockIdx.y * BM;
    const int bn = blockIdx.x * BN;
    const int wm = (wid >> 2) * 64;   // 2 warps in m
    const int wn = (wid & 3) * 32;    // 4 warps in n

    // --- cp.async addressing: thread -> row tid>>3 (0..31), granule tid&7 ---
    const char* a_src = (const char*)(g_XH +
        (size_t)(bm + (tid >> 3)) * D_DIM + (tid & 7) * 8);
    const char* b_src = (const char*)(g_WTH +
        (size_t)(bn + (tid >> 3)) * D_DIM + (tid & 7) * 8);
    const uint32_t sdst0 = (uint32_t)((tid >> 3) * 128) +
                           ((uint32_t)((tid & 7) ^ ((tid >> 3) & 7)) << 4);

    // 8 granules/thread/stage: A j0..3 rows +32j, B j0..3. 3 chunks: 4/2/2.
    auto load_chunk = [&](int kt, uint32_t sb, int c) {
        const char* ak = a_src + (size_t)kt * (BK * 2);
        const char* bk = b_src + (size_t)kt * (BK * 2);
        if (c == 0) {
#pragma unroll
            for (int j = 0; j < 4; j++)
                cp_async16(sb + sdst0 + j * 4096,
                           ak + (size_t)j * 32 * D_DIM * 2);
        } else if (c == 1) {
#pragma unroll
            for (int j = 0; j < 2; j++)
                cp_async16(sb + A_TILE_BYTES + sdst0 + j * 4096,
                           bk + (size_t)j * 32 * D_DIM * 2);
        } else {
#pragma unroll
            for (int j = 2; j < 4; j++)
                cp_async16(sb + A_TILE_BYTES + sdst0 + j * 4096,
                           bk + (size_t)j * 32 * D_DIM * 2);
        }
    };

    // --- ldmatrix addressing ---
    const int arow_l = (l & 15);
    const int akg0 = (l >> 4);
    const int brow_off = (l & 7) + ((l >> 4) << 3);
    const int bkg0 = (l >> 3) & 1;
    const uint32_t a_base = (uint32_t)((wm + arow_l) * 128);
    const uint32_t b_base = (uint32_t)((wn + brow_off) * 128) + A_TILE_BYTES;
    const uint32_t kxor = (uint32_t)(l & 7);

    float acc[4][4][4] = {};

    // --- prologue: fill stages 0,1 ---
#pragma unroll
    for (int s = 0; s < STAGES - 1; s++) {
        load_chunk(s, sbase + (uint32_t)s * STAGE_BYTES, 0);
        load_chunk(s, sbase + (uint32_t)s * STAGE_BYTES, 1);
        load_chunk(s, sbase + (uint32_t)s * STAGE_BYTES, 2);
        cp_commit();
    }
    asm volatile("cp.async.wait_group %0;" :: "n"(STAGES - 2) : "memory");
    __syncthreads();

    int cs = 0, ps = STAGES - 1;   // current slot, prefetch slot
    for (int kt = 0; kt < KTILES; kt++) {
        const uint32_t stg = sbase + (uint32_t)cs * STAGE_BYTES;
        const uint32_t pstg = sbase + (uint32_t)ps * STAGE_BYTES;
        const int pf = kt + STAGES - 1;
        const bool pv = pf < KTILES;

#pragma unroll
        for (int ks = 0; ks < 4; ks++) {
            if (ks < 3 && pv) load_chunk(pf, pstg, ks);
            // single-buffered fragments (TLP hides the RAW stall)
            uint32_t A[4][4], B[2][4];
#pragma unroll
            for (int mt = 0; mt < 4; mt++)
                ldsm_x4(A[mt], stg + a_base + mt * 2048 +
                               ((((uint32_t)(2 * ks) + akg0) ^ kxor) << 4));
#pragma unroll
            for (int p = 0; p < 2; p++)
                ldsm_x4(B[p], stg + b_base + p * 2048 +
                              ((((uint32_t)(2 * ks) + bkg0) ^ kxor) << 4));
#pragma unroll
            for (int mt = 0; mt < 4; mt++)
#pragma unroll
                for (int p = 0; p < 2; p++) {
                    mma16816(acc[mt][2 * p],     A[mt], B[p][0], B[p][1]);
                    mma16816(acc[mt][2 * p + 1], A[mt], B[p][2], B[p][3]);
                }
        }
        cp_commit();
        asm volatile("cp.async.wait_group %0;" :: "n"(STAGES - 2) : "memory");
        __syncthreads();
        cs = (cs == STAGES - 1) ? 0 : cs + 1;
        ps = (ps == STAGES - 1) ? 0 : ps + 1;
    }

    // --- epilogue: y = acc + bias ---
    const int grp = l >> 2, tig = l & 3;
#pragma unroll
    for (int mt = 0; mt < 4; mt++) {
        const size_t row0 = (size_t)(bm + wm + mt * 16 + grp);
#pragma unroll
        for (int nt = 0; nt < 4; nt++) {
            const int col = bn + wn + nt * 8 + tig * 2;
            const float2 bv = *reinterpret_cast<const float2*>(bias + col);
            float2 v0, v1;
            v0.x = acc[mt][nt][0] + bv.x;
            v0.y = acc[mt][nt][1] + bv.y;
            v1.x = acc[mt][nt][2] + bv.x;
            v1.y = acc[mt][nt][3] + bv.y;
            *reinterpret_cast<float2*>(out + row0 * D_DIM + col) = v0;
            *reinterpret_cast<float2*>(out + (row0 + 8) * D_DIM + col) = v1;
        }
    }
}

// ---------------------------------------------------------------------------
// Launch
// ---------------------------------------------------------------------------
extern "C" void kernel_launch(void* const* d_in, const int* in_sizes, int n_in,
                              void* d_out, int out_size) {
    const float* x    = (const float*)d_in[0];
    const float* W    = (const float*)d_in[1];
    const float* bias = (const float*)d_in[2];
    float* out = (float*)d_out;

    cudaFuncSetAttribute(gemm_f16_kernel,
                         cudaFuncAttributeMaxDynamicSharedMemorySize, SMEM_SIZE);

    prep_kernel<<<XBLK2 + 64 * 64, 256>>>((const float4*)x, W);
    gemm_f16_kernel<<<dim3(D_DIM / BN, M_DIM / BM), THREADS, SMEM_SIZE>>>(
        bias, out);
}

// round 17
// speedup vs baseline: 1.1660x; 1.1660x over previous
#include <cuda_runtime.h>
#include <cuda_fp16.h>
#include <cstdint>
#include <cstddef>

// ============================================================================
// SparseLinear: y[8192,4096] = x[8192,4096] @ W[4096,4096] + bias[4096]
// Dense fp16 mma.sync GEMM (tcgen05 blocked by compute_103 PTX target).
// R17: 2 CTAs/SM *without* shrinking the warp tile (R16's mistake).
//      128 threads/CTA, 4 warps (2m x 2n), warp tile 64x64 (ldsm:mma=0.25),
//      BM=BN=128, BK=64, 3 stages, fragment double-buffering as in R12/R15.
//      Cross-CTA overlap covers barrier waits + prologue/epilogue drain.
// ============================================================================

#define D_DIM 4096
#define M_DIM 8192
#define BM 128
#define BN 128
#define BK 64
#define STAGES 3
#define KTILES (D_DIM / BK)            // 64
#define THREADS 128
#define A_TILE_BYTES (BM * BK * 2)     // 16384
#define B_TILE_BYTES (BN * BK * 2)     // 16384
#define STAGE_BYTES (A_TILE_BYTES + B_TILE_BYTES)   // 32768
#define SMEM_SIZE (STAGES * STAGE_BYTES)            // 98304

__device__ __align__(256) __half g_XH[(size_t)M_DIM * D_DIM];
__device__ __align__(256) __half g_WTH[(size_t)D_DIM * D_DIM];

// ---------------------------------------------------------------------------
// helpers
// ---------------------------------------------------------------------------
__device__ __forceinline__ uint32_t smem_u32(const void* p) {
    uint32_t a;
    asm("{ .reg .u64 t; cvta.to.shared.u64 t, %1; cvt.u32.u64 %0, t; }"
        : "=r"(a) : "l"(p));
    return a;
}

__device__ __forceinline__ void cp_async16(uint32_t dst, const void* src) {
    asm volatile("cp.async.cg.shared.global [%0], [%1], 16;"
                 :: "r"(dst), "l"(src));
}
__device__ __forceinline__ void cp_commit() {
    asm volatile("cp.async.commit_group;" ::: "memory");
}

__device__ __forceinline__ void ldsm_x4(uint32_t* r, uint32_t addr) {
    asm volatile("ldmatrix.sync.aligned.m8n8.x4.shared.b16 {%0,%1,%2,%3}, [%4];"
                 : "=r"(r[0]), "=r"(r[1]), "=r"(r[2]), "=r"(r[3])
                 : "r"(addr));
}

__device__ __forceinline__ void mma16816(float* c, const uint32_t* a,
                                         uint32_t b0, uint32_t b1) {
    asm volatile(
        "mma.sync.aligned.m16n8k16.row.col.f32.f16.f16.f32 "
        "{%0,%1,%2,%3}, {%4,%5,%6,%7}, {%8,%9}, {%0,%1,%2,%3};"
        : "+f"(c[0]), "+f"(c[1]), "+f"(c[2]), "+f"(c[3])
        : "r"(a[0]), "r"(a[1]), "r"(a[2]), "r"(a[3]), "r"(b0), "r"(b1));
}

// ---------------------------------------------------------------------------
// Merged prep (proven R15): x convert 32B/thread; 64x64 W-transpose tiles.
// ---------------------------------------------------------------------------
#define XBLK2 ((int)((size_t)M_DIM * D_DIM / 8 / 256))   // 16384

__global__ void prep_kernel(const float4* __restrict__ x,
                            const float* __restrict__ W) {
    if (blockIdx.x < XBLK2) {
        size_t i = (size_t)blockIdx.x * 256 + threadIdx.x;
        float4 v0 = x[2 * i];
        float4 v1 = x[2 * i + 1];
        __half2 h0 = __floats2half2_rn(v0.x, v0.y);
        __half2 h1 = __floats2half2_rn(v0.z, v0.w);
        __half2 h2 = __floats2half2_rn(v1.x, v1.y);
        __half2 h3 = __floats2half2_rn(v1.z, v1.w);
        uint4 o;
        o.x = *reinterpret_cast<uint32_t*>(&h0);
        o.y = *reinterpret_cast<uint32_t*>(&h1);
        o.z = *reinterpret_cast<uint32_t*>(&h2);
        o.w = *reinterpret_cast<uint32_t*>(&h3);
        reinterpret_cast<uint4*>(g_XH)[i] = o;
    } else {
        __shared__ float t[64][65];    // t[n_local][k_local]
        int b = blockIdx.x - XBLK2;                    // 64 x 64 tile grid
        int bx = (b & 63) * 64, by = (b >> 6) * 64;    // bx: n, by: k
        const int nx = threadIdx.x & 63, ky = threadIdx.x >> 6;
#pragma unroll
        for (int i = 0; i < 16; i++)
            t[nx][ky + i * 4] = W[(size_t)(by + ky + i * 4) * D_DIM + bx + nx];
        __syncthreads();
#pragma unroll
        for (int i = 0; i < 8; i++) {
            int idx = threadIdx.x + i * 256;
            int nl = idx >> 5, c = idx & 31;
            float va = t[nl][2 * c];
            float vb = t[nl][2 * c + 1];
            __half2 h = __floats2half2_rn(va, vb);
            *reinterpret_cast<uint32_t*>(
                g_WTH + (size_t)(bx + nl) * D_DIM + by + 2 * c) =
                *reinterpret_cast<uint32_t*>(&h);
        }
    }
}

// ---------------------------------------------------------------------------
// GEMM. grid (32, 64) = 2048 CTAs, 2 CTAs/SM. 128 thr = 4 warps (2m x 2n),
// warp tile 64x64. SMEM stage: [A 128x64 | B 128x64], 128B rows, XOR swizzle.
// ---------------------------------------------------------------------------
__global__ __launch_bounds__(THREADS, 2)
void gemm_f16_kernel(const float* __restrict__ bias, float* __restrict__ out) {
    extern __shared__ char smem[];
    const uint32_t sbase = smem_u32(smem);
    const int tid = threadIdx.x;
    const int wid = tid >> 5;          // 0..3
    const int l = tid & 31;
    const int bm = blockIdx.y * BM;
    const int bn = blockIdx.x * BN;
    const int wm = (wid >> 1) * 64;    // 2 warps in m
    const int wn = (wid & 1) * 64;     // 2 warps in n

    // --- cp.async: 128 thr -> rows r0=tid>>3 (0..15), granule g0=tid&7;
    //     16 granules/thread/stage (A j0..7, B j0..7; row step 16).
    const int r0 = tid >> 3;
    const int g0 = tid & 7;
    const char* a_src = (const char*)(g_XH + (size_t)(bm + r0) * D_DIM + g0 * 8);
    const char* b_src = (const char*)(g_WTH + (size_t)(bn + r0) * D_DIM + g0 * 8);
    const uint32_t sdst0 = (uint32_t)(r0 * 128) +
                           ((uint32_t)(g0 ^ (r0 & 7)) << 4);
    const size_t gstep = (size_t)16 * D_DIM * 2;   // 16 rows

    // chunk c in 0..3: c0 A j0-3, c1 A j4-7, c2 B j0-3, c3 B j4-7
    auto load_chunk = [&](int kt, uint32_t sb, int c) {
        const char* ak = a_src + (size_t)kt * (BK * 2);
        const char* bk = b_src + (size_t)kt * (BK * 2);
        if (c == 0) {
#pragma unroll
            for (int j = 0; j < 4; j++)
                cp_async16(sb + sdst0 + j * 2048, ak + (size_t)j * gstep);
        } else if (c == 1) {
#pragma unroll
            for (int j = 4; j < 8; j++)
                cp_async16(sb + sdst0 + j * 2048, ak + (size_t)j * gstep);
        } else if (c == 2) {
#pragma unroll
            for (int j = 0; j < 4; j++)
                cp_async16(sb + A_TILE_BYTES + sdst0 + j * 2048,
                           bk + (size_t)j * gstep);
        } else {
#pragma unroll
            for (int j = 4; j < 8; j++)
                cp_async16(sb + A_TILE_BYTES + sdst0 + j * 2048,
                           bk + (size_t)j * gstep);
        }
    };

    // --- ldmatrix addressing (identical to R12/R15 conventions) ---
    const int arow_l = (l & 15);
    const int akg0 = (l >> 4);
    const int brow_off = (l & 7) + ((l >> 4) << 3);
    const int bkg0 = (l >> 3) & 1;
    const uint32_t a_base = (uint32_t)((wm + arow_l) * 128);
    const uint32_t b_base = (uint32_t)((wn + brow_off) * 128) + A_TILE_BYTES;
    const uint32_t kxor = (uint32_t)(l & 7);

    auto load_frags = [&](uint32_t stg, int ks,
                          uint32_t (&A)[4][4], uint32_t (&B)[4][4]) {
#pragma unroll
        for (int mt = 0; mt < 4; mt++)
            ldsm_x4(A[mt], stg + a_base + mt * 2048 +
                           ((((uint32_t)(2 * ks) + akg0) ^ kxor) << 4));
#pragma unroll
        for (int p = 0; p < 4; p++)
            ldsm_x4(B[p], stg + b_base + p * 2048 +
                          ((((uint32_t)(2 * ks) + bkg0) ^ kxor) << 4));
    };

    float acc[4][8][4] = {};
    uint32_t Abuf[2][4][4], Bbuf[2][4][4];

    auto mma_all = [&](uint32_t (&A)[4][4], uint32_t (&B)[4][4]) {
#pragma unroll
        for (int mt = 0; mt < 4; mt++)
#pragma unroll
            for (int p = 0; p < 4; p++) {
                mma16816(acc[mt][2 * p],     A[mt], B[p][0], B[p][1]);
                mma16816(acc[mt][2 * p + 1], A[mt], B[p][2], B[p][3]);
            }
    };

    // --- prologue: fill stages 0,1 ---
#pragma unroll
    for (int s = 0; s < STAGES - 1; s++) {
        const uint32_t sb = sbase + (uint32_t)s * STAGE_BYTES;
#pragma unroll
        for (int c = 0; c < 4; c++) load_chunk(s, sb, c);
        cp_commit();
    }
    asm volatile("cp.async.wait_group %0;" :: "n"(STAGES - 2) : "memory");
    __syncthreads();
    load_frags(sbase, 0, Abuf[0], Bbuf[0]);

    int cs = 0, ps = STAGES - 1;
    for (int kt = 0; kt < KTILES; kt++) {
        const uint32_t stg = sbase + (uint32_t)cs * STAGE_BYTES;
        const uint32_t pstg = sbase + (uint32_t)ps * STAGE_BYTES;
        const int pf = kt + STAGES - 1;
        const bool pv = pf < KTILES;

#pragma unroll
        for (int ks = 0; ks < 4; ks++) {
            if (pv) load_chunk(pf, pstg, ks);      // 4 chunks over 4 steps
            if (ks < 3)
                load_frags(stg, ks + 1, Abuf[(ks + 1) & 1], Bbuf[(ks + 1) & 1]);
            mma_all(Abuf[ks & 1], Bbuf[ks & 1]);
        }
        cp_commit();
        asm volatile("cp.async.wait_group %0;" :: "n"(STAGES - 2) : "memory");
        __syncthreads();
        cs = (cs == STAGES - 1) ? 0 : cs + 1;
        if (kt + 1 < KTILES)
            load_frags(sbase + (uint32_t)cs * STAGE_BYTES, 0, Abuf[0], Bbuf[0]);
        ps = (ps == STAGES - 1) ? 0 : ps + 1;
    }

    // --- epilogue: y = acc + bias ---
    const int grp = l >> 2, tig = l & 3;
#pragma unroll
    for (int mt = 0; mt < 4; mt++) {
        const size_t row0 = (size_t)(bm + wm + mt * 16 + grp);
#pragma unroll
        for (int nt = 0; nt < 8; nt++) {
            const int col = bn + wn + nt * 8 + tig * 2;
            const float2 bv = *reinterpret_cast<const float2*>(bias + col);
            float2 v0, v1;
            v0.x = acc[mt][nt][0] + bv.x;
            v0.y = acc[mt][nt][1] + bv.y;
            v1.x = acc[mt][nt][2] + bv.x;
            v1.y = acc[mt][nt][3] + bv.y;
            *reinterpret_cast<float2*>(out + row0 * D_DIM + col) = v0;
            *reinterpret_cast<float2*>(out + (row0 + 8) * D_DIM + col) = v1;
        }
    }
}

// ---------------------------------------------------------------------------
// Launch
// ---------------------------------------------------------------------------
extern "C" void kernel_launch(void* const* d_in, const int* in_sizes, int n_in,
                              void* d_out, int out_size) {
    const float* x    = (const float*)d_in[0];
    const float* W    = (const float*)d_in[1];
    const float* bias = (const float*)d_in[2];
    float* out = (float*)d_out;

    cudaFuncSetAttribute(gemm_f16_kernel,
                         cudaFuncAttributeMaxDynamicSharedMemorySize, SMEM_SIZE);

    prep_kernel<<<XBLK2 + 64 * 64, 256>>>((const float4*)x, W);
    gemm_f16_kernel<<<dim3(D_DIM / BN, M_DIM / BM), THREADS, SMEM_SIZE>>>(
        bias, out);
}